// round 13
// baseline (speedup 1.0000x reference)
#include <cuda_runtime.h>
#include <cuda_bf16.h>
#include <math.h>

// Problem constants
#define BB 8
#define TT 2048
#define DIN 256
#define HH 512
#define G4 2048          // 4*H
#define MM (BB*TT)       // 16384
#define NCTA 96
#define L0_CTAS 32

// ---------------- device scratch ----------------
__device__ float g_wx0[(size_t)MM * G4];   // 128 MB: x@W0^T + (w0_b+u0_b)
__device__ float g_h1[2][HH * BB];         // ping-pong h of layer0, layout [j][b]
__device__ float g_h2[2][HH * BB];         // ping-pong h of layer1
__device__ unsigned g_bar;                 // global barrier counter

// ---------------- shared memory layout (floats) ----------------
// wS   : [K][SW]  SW = R+4 pad      max 1024*36 = 36864 floats
// srcS : [K][8]                     max 8192 floats
// redS : [8*R4][34]                 max 4352 floats
#define OFF_SRC  36864
#define OFF_RED  45056
#define SMEM_FLOATS 53760
#define SMEM_BYTES (SMEM_FLOATS * 4)   // 215040 < 227KB limit

typedef unsigned long long u64;

__device__ __forceinline__ u64 pk2(float x) {
    u64 r; asm("mov.b64 %0, {%1, %1};" : "=l"(r) : "f"(x)); return r;
}
__device__ __forceinline__ void fma2(u64& a, u64 b, u64 c) {
    asm("fma.rn.f32x2 %0, %1, %2, %0;" : "+l"(a) : "l"(b), "l"(c));
}
__device__ __forceinline__ u64 addp(u64 a, u64 b) {
    u64 r; asm("add.rn.f32x2 %0, %1, %2;" : "=l"(r) : "l"(a), "l"(b)); return r;
}
__device__ __forceinline__ void upk(float& lo, float& hi, u64 v) {
    asm("mov.b64 {%0, %1}, %2;" : "=f"(lo), "=f"(hi) : "l"(v));
}
__device__ __forceinline__ float4 ldcg4(const float4* p) { return __ldcg(p); }
__device__ __forceinline__ float fast_sig(float x) {
    return __fdividef(1.f, 1.f + __expf(-x));
}
__device__ __forceinline__ float fast_tanh(float x) {
    float e = __expf(2.f * x);
    return 1.f - __fdividef(2.f, e + 1.f);
}

// 4 packed FMAs: acc[AOFF..AOFF+3] += (w,w) * hpairs
#define FMA_ROW2(AOFF, WV)                                   \
    { u64 wp = pk2(WV);                                      \
      fma2(acc[AOFF+0], wp, hA.x); fma2(acc[AOFF+1], wp, hA.y); \
      fma2(acc[AOFF+2], wp, hB.x); fma2(acc[AOFF+3], wp, hB.y); }

template <int LAYER, int R, int K, int U>
__device__ void run_layer(const float* __restrict__ wA,
                          const float* __restrict__ wB,
                          const float* __restrict__ bA,
                          const float* __restrict__ bB,
                          int ubase, float* sm, float* __restrict__ out)
{
    const int t = threadIdx.x;
    const int lane = t & 31;
    const int w = t >> 5;
    constexpr int R4  = R / 4;
    constexpr int SW  = R + 4;
    constexpr int NKG = 256 / R4;    // 16 (L0) / 32 (L1)
    constexpr int KCH = K / NKG;     // 32 both
    constexpr int KSH = (K == 512) ? 9 : 10;
    constexpr int UPD = U * 8;       // 128 (L0) / 64 (L1)

    float* wS   = sm;
    float* srcS = sm + OFF_SRC;
    float* redS = sm + OFF_RED;

    // ---- one-time weight load (transposed [k][row], padded) ----
    for (int e = t; e < R * K; e += 256) {
        int k  = e & (K - 1);
        int rr = e >> KSH;
        int g  = (rr / U) * 512 + ubase + (rr % U);
        float v;
        if (LAYER == 0) v = wA[g * 512 + k];
        else            v = (k < 512) ? wA[g * 512 + k] : wB[g * 512 + (k - 512)];
        wS[k * SW + rr] = v;
    }

    const int uu = t >> 3;
    const int ub = t & 7;

    float biasv[4] = {0.f, 0.f, 0.f, 0.f};
    if (LAYER == 1 && t < UPD) {
        #pragma unroll
        for (int g = 0; g < 4; ++g) {
            int gi = g * 512 + ubase + uu;
            biasv[g] = bA[gi] + bB[gi];
        }
    }
    __syncthreads();

    float c_state = 0.f;
    const int jg = t & (R4 - 1);
    const int kg = t >> ((LAYER == 0) ? 4 : 3);

    // wx prefetch (L0 only): initial round
    float wxv[4] = {0.f, 0.f, 0.f, 0.f};
    const float* wxrow = (LAYER == 0)
        ? &g_wx0[((size_t)(ub * TT)) * G4 + ubase + uu] : nullptr;
    if (LAYER == 0 && t < UPD) {
        #pragma unroll
        for (int g = 0; g < 4; ++g) wxv[g] = __ldg(wxrow + g * 512);
    }

    for (int r = 0; r <= TT; ++r) {
        const bool active = (LAYER == 0) ? (r < TT) : (r >= 1);

        if (active) {
            const int slot = (r + 1) & 1;   // (r-1) mod 2
            // slice-aligned warp-local stage
            float4* dst = (float4*)srcS;
            if (LAYER == 0) {
                const float4* s1 = (const float4*)g_h1[slot];
                const int base = 128 * w + lane;
                dst[base]      = ldcg4(s1 + base);
                dst[base + 32] = ldcg4(s1 + base + 32);
                dst[base + 64] = ldcg4(s1 + base + 64);
                dst[base + 96] = ldcg4(s1 + base + 96);
            } else {
                const float4* s1 = (const float4*)g_h1[slot];
                const float4* s2 = (const float4*)g_h2[slot];
                const float4* src = (w < 4) ? (s1 + 256 * w) : (s2 + 256 * (w - 4));
                float4* d = dst + 256 * w;
                #pragma unroll
                for (int i = 0; i < 8; ++i)
                    d[lane + i * 32] = ldcg4(src + lane + i * 32);
            }
            __syncwarp();

            u64 acc[16];
            #pragma unroll
            for (int i = 0; i < 16; ++i) acc[i] = 0ull;
            const float4* w4 = (const float4*)wS;
            const int kbase = kg * KCH;
            #pragma unroll 8
            for (int kk = 0; kk < KCH; ++kk) {
                const int k = kbase + kk;
                float4 wv = w4[k * (SW / 4) + jg];
                const ulonglong2* hsrc = (const ulonglong2*)(srcS + k * 8);
                ulonglong2 hA = hsrc[0];   // batch pairs (0,1),(2,3)
                ulonglong2 hB = hsrc[1];   // batch pairs (4,5),(6,7)
                FMA_ROW2(0,  wv.x)
                FMA_ROW2(4,  wv.y)
                FMA_ROW2(8,  wv.z)
                FMA_ROW2(12, wv.w)
            }

            // in-warp pre-reduction across k-groups -> 8 partial groups
            if (LAYER == 0) {
                // kg pair (2w, 2w+1): lane^16 flips kg LSB, jg (t&15) unchanged
                #pragma unroll
                for (int i = 0; i < 16; ++i)
                    acc[i] = addp(acc[i], __shfl_xor_sync(0xffffffffu, acc[i], 16));
                if (lane < 16) {
                    u64* rb = (u64*)(redS + (w * R4 + jg) * 34);
                    #pragma unroll
                    for (int i = 0; i < 16; ++i) rb[i] = acc[i];
                }
            } else {
                // kg quad (4w..4w+3): lane^8 -> kg±1, lane^16 -> kg±2, jg (t&7) same
                #pragma unroll
                for (int i = 0; i < 16; ++i) {
                    acc[i] = addp(acc[i], __shfl_xor_sync(0xffffffffu, acc[i], 8));
                    acc[i] = addp(acc[i], __shfl_xor_sync(0xffffffffu, acc[i], 16));
                }
                if (lane < 8) {
                    u64* rb = (u64*)(redS + (w * R4 + jg) * 34);
                    #pragma unroll
                    for (int i = 0; i < 16; ++i) rb[i] = acc[i];
                }
            }
        }
        __syncthreads();   // redS ready for the merged tail

        float h_def = 0.f;   // deferred output value (L1)
        if (active && t < UPD) {
            float s4[4];
            #pragma unroll
            for (int g = 0; g < 4; ++g) {
                const int row = g * U + uu;
                const int jgg = row >> 2, rrg = row & 3;
                float s = (LAYER == 0) ? wxv[g] : biasv[g];
                #pragma unroll
                for (int k2 = 0; k2 < 8; ++k2)
                    s += redS[(k2 * R4 + jgg) * 34 + rrg * 8 + ub];
                s4[g] = s;
            }
            float si = fast_sig(s4[0]);
            float sf = fast_sig(s4[1]);
            float tg = fast_tanh(s4[2]);
            float so = fast_sig(s4[3]);
            c_state = sf * c_state + si * tg;
            float h = so * fmaxf(c_state, 0.f);
            const int j = ubase + uu;
            const int slotw = r & 1;
            if (LAYER == 0) {
                __stcg(&g_h1[slotw][j * 8 + ub], h);
                if (r == TT - 1) {
                    out[8388608 + ub * 512 + j] = h;        // hh[0]
                    out[8396800 + ub * 512 + j] = c_state;  // cc[0]
                }
            } else {
                __stcg(&g_h2[slotw][j * 8 + ub], h);
                h_def = h;
                if (r == TT) {   // last epoch: no barrier follows, store now
                    out[((size_t)(ub * TT + (r - 1))) * HH + j] = h;
                    out[8388608 + 4096 + ub * 512 + j] = h;        // hh[1]
                    out[8396800 + 4096 + ub * 512 + j] = c_state;  // cc[1]
                }
            }
        }

        // prefetch next round's wx (lands during the barrier spin)
        if (LAYER == 0 && t < UPD && r + 1 < TT) {
            const float* p = wxrow + (size_t)(r + 1) * G4;
            #pragma unroll
            for (int g = 0; g < 4; ++g) wxv[g] = __ldg(p + g * 512);
        }

        if (r < TT) {
            if (t < UPD) asm volatile("bar.sync 1, %0;" :: "n"(UPD) : "memory");
            if (t == 0)
                asm volatile("red.release.gpu.global.add.u32 [%0], 1;"
                             :: "l"(&g_bar) : "memory");
            // deferred output store: overlaps t0's spin
            if (LAYER == 1 && active && t < UPD) {
                const int j = ubase + uu;
                out[((size_t)(ub * TT + (r - 1))) * HH + j] = h_def;
            }
            if (t == 0) {
                const unsigned target = (unsigned)NCTA * (unsigned)(r + 1);
                unsigned v;
                do {
                    asm volatile("ld.acquire.gpu.global.u32 %0, [%1];"
                                 : "=r"(v) : "l"(&g_bar) : "memory");
                } while (v < target);
            }
            __syncthreads();
        }
    }
}

__global__ void __launch_bounds__(256, 1)
lstm_persist(const float* __restrict__ u0w,
             const float* __restrict__ w1w, const float* __restrict__ u1w,
             const float* __restrict__ w1b, const float* __restrict__ u1b,
             float* __restrict__ out)
{
    extern __shared__ float sm[];
    const int cta = blockIdx.x;
    if (cta < L0_CTAS) {
        run_layer<0, 64, 512, 16>(u0w, nullptr, nullptr, nullptr, cta * 16, sm, out);
    } else {
        run_layer<1, 32, 1024, 8>(w1w, u1w, w1b, u1b, (cta - L0_CTAS) * 8, sm, out);
    }
}

// ---------------- kernel 1: wx0 = x @ w0^T + (w0_b + u0_b), plus state reset ----------------
__global__ void wx_gemm(const float* __restrict__ X, const float* __restrict__ W,
                        const float* __restrict__ b0, const float* __restrict__ ub0)
{
    __shared__ float As[16][128];
    __shared__ float Bs[16][128];
    const int bn = blockIdx.x, bm = blockIdx.y;
    const int t = threadIdx.x;

    if (bn == 0 && bm == 0) {
        float* h1f = (float*)g_h1;
        float* h2f = (float*)g_h2;
        for (int i = t; i < 2 * HH * BB; i += 256) { h1f[i] = 0.f; h2f[i] = 0.f; }
        if (t == 0) g_bar = 0u;
    }

    const int tm = t & 15, tn = t >> 4;
    u64 accp[8][4];
    #pragma unroll
    for (int i = 0; i < 8; ++i)
        #pragma unroll
        for (int j = 0; j < 4; ++j) accp[i][j] = 0ull;

    for (int kt = 0; kt < DIN; kt += 16) {
        #pragma unroll
        for (int i = 0; i < 2; ++i) {
            int f = t * 2 + i;
            int row = f >> 2, kq = f & 3;
            float4 a = *(const float4*)&X[(size_t)(bm * 128 + row) * DIN + kt + kq * 4];
            As[kq * 4 + 0][row] = a.x; As[kq * 4 + 1][row] = a.y;
            As[kq * 4 + 2][row] = a.z; As[kq * 4 + 3][row] = a.w;
            float4 bv = *(const float4*)&W[(size_t)(bn * 128 + row) * DIN + kt + kq * 4];
            Bs[kq * 4 + 0][row] = bv.x; Bs[kq * 4 + 1][row] = bv.y;
            Bs[kq * 4 + 2][row] = bv.z; Bs[kq * 4 + 3][row] = bv.w;
        }
        __syncthreads();
        #pragma unroll
        for (int k = 0; k < 16; ++k) {
            float4 a0 = *(const float4*)&As[k][tm * 8];
            float4 a1 = *(const float4*)&As[k][tm * 8 + 4];
            const ulonglong2* bp = (const ulonglong2*)&Bs[k][tn * 8];
            ulonglong2 c01 = bp[0];
            ulonglong2 c23 = bp[1];
            float av[8] = {a0.x, a0.y, a0.z, a0.w, a1.x, a1.y, a1.z, a1.w};
            #pragma unroll
            for (int i = 0; i < 8; ++i) {
                u64 wp = pk2(av[i]);
                fma2(accp[i][0], wp, c01.x);
                fma2(accp[i][1], wp, c01.y);
                fma2(accp[i][2], wp, c23.x);
                fma2(accp[i][3], wp, c23.y);
            }
        }
        __syncthreads();
    }

    const int gbase = bn * 128 + tn * 8;
    float bias[8];
    #pragma unroll
    for (int j = 0; j < 8; ++j) bias[j] = __ldg(&b0[gbase + j]) + __ldg(&ub0[gbase + j]);
    #pragma unroll
    for (int i = 0; i < 8; ++i) {
        const int m = bm * 128 + tm * 8 + i;
        float v[8];
        #pragma unroll
        for (int p = 0; p < 4; ++p) upk(v[2 * p], v[2 * p + 1], accp[i][p]);
        float4 o0 = make_float4(v[0] + bias[0], v[1] + bias[1],
                                v[2] + bias[2], v[3] + bias[3]);
        float4 o1 = make_float4(v[4] + bias[4], v[5] + bias[5],
                                v[6] + bias[6], v[7] + bias[7]);
        *(float4*)&g_wx0[(size_t)m * G4 + gbase]     = o0;
        *(float4*)&g_wx0[(size_t)m * G4 + gbase + 4] = o1;
    }
}

extern "C" void kernel_launch(void* const* d_in, const int* in_sizes, int n_in,
                              void* d_out, int out_size)
{
    const float* x    = (const float*)d_in[0];
    const float* w0_w = (const float*)d_in[1];
    const float* w0_b = (const float*)d_in[2];
    const float* u0_w = (const float*)d_in[3];
    const float* u0_b = (const float*)d_in[4];
    const float* w1_w = (const float*)d_in[5];
    const float* w1_b = (const float*)d_in[6];
    const float* u1_w = (const float*)d_in[7];
    const float* u1_b = (const float*)d_in[8];
    float* out = (float*)d_out;

    static int attr_done = 0;
    if (!attr_done) {
        cudaFuncSetAttribute(lstm_persist, cudaFuncAttributeMaxDynamicSharedMemorySize, SMEM_BYTES);
        attr_done = 1;
    }

    wx_gemm<<<dim3(G4 / 128, MM / 128), 256>>>(x, w0_w, w0_b, u0_b);
    lstm_persist<<<NCTA, 256, SMEM_BYTES>>>(u0_w, w1_w, u1_w, w1_b, u1_b, out);
}

// round 14
// speedup vs baseline: 1.0534x; 1.0534x over previous
#include <cuda_runtime.h>
#include <cuda_bf16.h>
#include <math.h>

// Problem constants
#define BB 8
#define TT 2048
#define DIN 256
#define HH 512
#define G4 2048          // 4*H
#define MM (BB*TT)       // 16384
#define NCTA 96
#define L0_CTAS 32

// ---------------- device scratch ----------------
__device__ float g_wx0[(size_t)MM * G4];   // 128 MB: x@W0^T + (w0_b+u0_b)
__device__ float g_h1[2][HH * BB];         // ping-pong h of layer0, layout [j][b]
__device__ float g_h2[2][HH * BB];         // ping-pong h of layer1
__device__ unsigned g_bar;                 // global barrier counter

// ---------------- shared memory layout (floats) ----------------
// wS   : [K][SW]  SW = R+4 pad      max 1024*36 = 36864 floats
// srcS : [K][8]                     max 8192 floats
// redS : [NKG*R4][36]               max 9216 floats (16B-aligned rows)
#define OFF_SRC  36864
#define OFF_RED  45056
#define SMEM_FLOATS 54272
#define SMEM_BYTES (SMEM_FLOATS * 4)   // 217088 < 227KB limit

typedef unsigned long long u64;

__device__ __forceinline__ u64 pk2(float x) {
    u64 r; asm("mov.b64 %0, {%1, %1};" : "=l"(r) : "f"(x)); return r;
}
__device__ __forceinline__ void fma2(u64& a, u64 b, u64 c) {
    asm("fma.rn.f32x2 %0, %1, %2, %0;" : "+l"(a) : "l"(b), "l"(c));
}
__device__ __forceinline__ u64 addp(u64 a, u64 b) {
    u64 r; asm("add.rn.f32x2 %0, %1, %2;" : "=l"(r) : "l"(a), "l"(b)); return r;
}
__device__ __forceinline__ void upk(float& lo, float& hi, u64 v) {
    asm("mov.b64 {%0, %1}, %2;" : "=f"(lo), "=f"(hi) : "l"(v));
}
__device__ __forceinline__ float4 ldcg4(const float4* p) { return __ldcg(p); }
__device__ __forceinline__ float fast_sig(float x) {
    return __fdividef(1.f, 1.f + __expf(-x));
}
__device__ __forceinline__ float fast_tanh(float x) {
    float e = __expf(2.f * x);
    return 1.f - __fdividef(2.f, e + 1.f);
}

// 4 packed FMAs: acc[AOFF..AOFF+3] += (w,w) * hpairs
#define FMA_ROW2(AOFF, WV)                                   \
    { u64 wp = pk2(WV);                                      \
      fma2(acc[AOFF+0], wp, hA.x); fma2(acc[AOFF+1], wp, hA.y); \
      fma2(acc[AOFF+2], wp, hB.x); fma2(acc[AOFF+3], wp, hB.y); }

template <int LAYER, int R, int K, int U>
__device__ void run_layer(const float* __restrict__ wA,
                          const float* __restrict__ wB,
                          const float* __restrict__ bA,
                          const float* __restrict__ bB,
                          int ubase, float* sm, float* __restrict__ out)
{
    const int t = threadIdx.x;
    const int lane = t & 31;
    const int w = t >> 5;
    constexpr int R4  = R / 4;
    constexpr int SW  = R + 4;
    constexpr int NKG = 256 / R4;    // 16 (L0) / 32 (L1)
    constexpr int KCH = K / NKG;     // 32 both
    constexpr int KSH = (K == 512) ? 9 : 10;
    constexpr int UPD = U * 8;       // 128 (L0) / 64 (L1)

    float* wS   = sm;
    float* srcS = sm + OFF_SRC;
    float* redS = sm + OFF_RED;

    // ---- one-time weight load (transposed [k][row], padded) ----
    // UNIT-MAJOR row order: local row rr -> unit rr>>2, gate rr&3
    for (int e = t; e < R * K; e += 256) {
        int k  = e & (K - 1);
        int rr = e >> KSH;
        int g  = (rr & 3) * 512 + ubase + (rr >> 2);
        float v;
        if (LAYER == 0) v = wA[g * 512 + k];
        else            v = (k < 512) ? wA[g * 512 + k] : wB[g * 512 + (k - 512)];
        wS[k * SW + rr] = v;
    }

    const int uu = t >> 3;
    const int ub = t & 7;

    float biasv[4] = {0.f, 0.f, 0.f, 0.f};
    if (LAYER == 1 && t < UPD) {
        #pragma unroll
        for (int g = 0; g < 4; ++g) {
            int gi = g * 512 + ubase + uu;
            biasv[g] = bA[gi] + bB[gi];
        }
    }
    __syncthreads();

    float c_state = 0.f;
    const int jg = t & (R4 - 1);
    const int kg = t >> ((LAYER == 0) ? 4 : 3);

    // wx prefetch (L0 only): initial round
    float wxv[4] = {0.f, 0.f, 0.f, 0.f};
    const float* wxrow = (LAYER == 0)
        ? &g_wx0[((size_t)(ub * TT)) * G4 + ubase + uu] : nullptr;
    if (LAYER == 0 && t < UPD) {
        #pragma unroll
        for (int g = 0; g < 4; ++g) wxv[g] = __ldg(wxrow + g * 512);
    }

    for (int r = 0; r <= TT; ++r) {
        const bool active = (LAYER == 0) ? (r < TT) : (r >= 1);

        if (active) {
            const int slot = (r + 1) & 1;   // (r-1) mod 2
            // slice-aligned warp-local stage
            float4* dst = (float4*)srcS;
            if (LAYER == 0) {
                const float4* s1 = (const float4*)g_h1[slot];
                const int base = 128 * w + lane;
                dst[base]      = ldcg4(s1 + base);
                dst[base + 32] = ldcg4(s1 + base + 32);
                dst[base + 64] = ldcg4(s1 + base + 64);
                dst[base + 96] = ldcg4(s1 + base + 96);
            } else {
                const float4* s1 = (const float4*)g_h1[slot];
                const float4* s2 = (const float4*)g_h2[slot];
                const float4* src = (w < 4) ? (s1 + 256 * w) : (s2 + 256 * (w - 4));
                float4* d = dst + 256 * w;
                #pragma unroll
                for (int i = 0; i < 8; ++i)
                    d[lane + i * 32] = ldcg4(src + lane + i * 32);
            }
            __syncwarp();

            u64 acc[16];
            #pragma unroll
            for (int i = 0; i < 16; ++i) acc[i] = 0ull;
            const float4* w4 = (const float4*)wS;
            const int kbase = kg * KCH;
            #pragma unroll 8
            for (int kk = 0; kk < KCH; ++kk) {
                const int k = kbase + kk;
                float4 wv = w4[k * (SW / 4) + jg];
                const ulonglong2* hsrc = (const ulonglong2*)(srcS + k * 8);
                ulonglong2 hA = hsrc[0];   // batch pairs (0,1),(2,3)
                ulonglong2 hB = hsrc[1];   // batch pairs (4,5),(6,7)
                FMA_ROW2(0,  wv.x)
                FMA_ROW2(4,  wv.y)
                FMA_ROW2(8,  wv.z)
                FMA_ROW2(12, wv.w)
            }
            // pair-major partial store: u64 index p*4+g, 8 x STS.128
            ulonglong2* rb = (ulonglong2*)(redS + (kg * R4 + jg) * 36);
            #pragma unroll
            for (int j = 0; j < 8; ++j) {
                const int p = j >> 1, g0 = (j & 1) * 2;
                rb[j] = make_ulonglong2(acc[g0 * 4 + p], acc[(g0 + 1) * 4 + p]);
            }
        }
        __syncthreads();   // redS ready for the merged tail

        float h_def = 0.f;   // deferred output value (L1)
        if (active && t < UPD) {
            // packed tail reduce: 2 x LDS.128 per k-group, f32x2 adds
            const int p = ub >> 1, hb = ub & 1;
            u64 sp0 = 0ull, sp1 = 0ull, sp2 = 0ull, sp3 = 0ull;
            #pragma unroll
            for (int k2 = 0; k2 < NKG; ++k2) {
                const ulonglong2* rbase =
                    (const ulonglong2*)(redS + (k2 * R4 + uu) * 36 + p * 8);
                ulonglong2 v0 = rbase[0];
                ulonglong2 v1 = rbase[1];
                sp0 = addp(sp0, v0.x); sp1 = addp(sp1, v0.y);
                sp2 = addp(sp2, v1.x); sp3 = addp(sp3, v1.y);
            }
            float s4[4];
            {
                float lo, hi;
                upk(lo, hi, sp0); s4[0] = hb ? hi : lo;
                upk(lo, hi, sp1); s4[1] = hb ? hi : lo;
                upk(lo, hi, sp2); s4[2] = hb ? hi : lo;
                upk(lo, hi, sp3); s4[3] = hb ? hi : lo;
            }
            #pragma unroll
            for (int g = 0; g < 4; ++g)
                s4[g] += (LAYER == 0) ? wxv[g] : biasv[g];

            float si = fast_sig(s4[0]);
            float sf = fast_sig(s4[1]);
            float tg = fast_tanh(s4[2]);
            float so = fast_sig(s4[3]);
            c_state = sf * c_state + si * tg;
            float h = so * fmaxf(c_state, 0.f);
            const int j = ubase + uu;
            const int slotw = r & 1;
            if (LAYER == 0) {
                __stcg(&g_h1[slotw][j * 8 + ub], h);
                if (r == TT - 1) {
                    out[8388608 + ub * 512 + j] = h;        // hh[0]
                    out[8396800 + ub * 512 + j] = c_state;  // cc[0]
                }
            } else {
                __stcg(&g_h2[slotw][j * 8 + ub], h);
                h_def = h;
                if (r == TT) {   // last epoch: no barrier follows, store now
                    out[((size_t)(ub * TT + (r - 1))) * HH + j] = h;
                    out[8388608 + 4096 + ub * 512 + j] = h;        // hh[1]
                    out[8396800 + 4096 + ub * 512 + j] = c_state;  // cc[1]
                }
            }
        }

        // prefetch next round's wx (lands during the barrier spin)
        if (LAYER == 0 && t < UPD && r + 1 < TT) {
            const float* p = wxrow + (size_t)(r + 1) * G4;
            #pragma unroll
            for (int g = 0; g < 4; ++g) wxv[g] = __ldg(p + g * 512);
        }

        if (r < TT) {
            if (t < UPD) asm volatile("bar.sync 1, %0;" :: "n"(UPD) : "memory");
            if (t == 0)
                asm volatile("red.release.gpu.global.add.u32 [%0], 1;"
                             :: "l"(&g_bar) : "memory");
            // deferred output store: overlaps t0's spin
            if (LAYER == 1 && active && t < UPD) {
                const int j = ubase + uu;
                out[((size_t)(ub * TT + (r - 1))) * HH + j] = h_def;
            }
            if (t == 0) {
                const unsigned target = (unsigned)NCTA * (unsigned)(r + 1);
                unsigned v;
                do {
                    asm volatile("ld.acquire.gpu.global.u32 %0, [%1];"
                                 : "=r"(v) : "l"(&g_bar) : "memory");
                } while (v < target);
            }
            __syncthreads();
        }
    }
}

__global__ void __launch_bounds__(256, 1)
lstm_persist(const float* __restrict__ u0w,
             const float* __restrict__ w1w, const float* __restrict__ u1w,
             const float* __restrict__ w1b, const float* __restrict__ u1b,
             float* __restrict__ out)
{
    extern __shared__ float sm[];
    const int cta = blockIdx.x;
    if (cta < L0_CTAS) {
        run_layer<0, 64, 512, 16>(u0w, nullptr, nullptr, nullptr, cta * 16, sm, out);
    } else {
        run_layer<1, 32, 1024, 8>(w1w, u1w, w1b, u1b, (cta - L0_CTAS) * 8, sm, out);
    }
}

// ---------------- kernel 1: wx0 = x @ w0^T + (w0_b + u0_b), plus state reset ----------------
__global__ void wx_gemm(const float* __restrict__ X, const float* __restrict__ W,
                        const float* __restrict__ b0, const float* __restrict__ ub0)
{
    __shared__ float As[16][128];
    __shared__ float Bs[16][128];
    const int bn = blockIdx.x, bm = blockIdx.y;
    const int t = threadIdx.x;

    if (bn == 0 && bm == 0) {
        float* h1f = (float*)g_h1;
        float* h2f = (float*)g_h2;
        for (int i = t; i < 2 * HH * BB; i += 256) { h1f[i] = 0.f; h2f[i] = 0.f; }
        if (t == 0) g_bar = 0u;
    }

    const int tm = t & 15, tn = t >> 4;
    u64 accp[8][4];
    #pragma unroll
    for (int i = 0; i < 8; ++i)
        #pragma unroll
        for (int j = 0; j < 4; ++j) accp[i][j] = 0ull;

    for (int kt = 0; kt < DIN; kt += 16) {
        #pragma unroll
        for (int i = 0; i < 2; ++i) {
            int f = t * 2 + i;
            int row = f >> 2, kq = f & 3;
            float4 a = *(const float4*)&X[(size_t)(bm * 128 + row) * DIN + kt + kq * 4];
            As[kq * 4 + 0][row] = a.x; As[kq * 4 + 1][row] = a.y;
            As[kq * 4 + 2][row] = a.z; As[kq * 4 + 3][row] = a.w;
            float4 bv = *(const float4*)&W[(size_t)(bn * 128 + row) * DIN + kt + kq * 4];
            Bs[kq * 4 + 0][row] = bv.x; Bs[kq * 4 + 1][row] = bv.y;
            Bs[kq * 4 + 2][row] = bv.z; Bs[kq * 4 + 3][row] = bv.w;
        }
        __syncthreads();
        #pragma unroll
        for (int k = 0; k < 16; ++k) {
            float4 a0 = *(const float4*)&As[k][tm * 8];
            float4 a1 = *(const float4*)&As[k][tm * 8 + 4];
            const ulonglong2* bp = (const ulonglong2*)&Bs[k][tn * 8];
            ulonglong2 c01 = bp[0];
            ulonglong2 c23 = bp[1];
            float av[8] = {a0.x, a0.y, a0.z, a0.w, a1.x, a1.y, a1.z, a1.w};
            #pragma unroll
            for (int i = 0; i < 8; ++i) {
                u64 wp = pk2(av[i]);
                fma2(accp[i][0], wp, c01.x);
                fma2(accp[i][1], wp, c01.y);
                fma2(accp[i][2], wp, c23.x);
                fma2(accp[i][3], wp, c23.y);
            }
        }
        __syncthreads();
    }

    const int gbase = bn * 128 + tn * 8;
    float bias[8];
    #pragma unroll
    for (int j = 0; j < 8; ++j) bias[j] = __ldg(&b0[gbase + j]) + __ldg(&ub0[gbase + j]);
    #pragma unroll
    for (int i = 0; i < 8; ++i) {
        const int m = bm * 128 + tm * 8 + i;
        float v[8];
        #pragma unroll
        for (int p = 0; p < 4; ++p) upk(v[2 * p], v[2 * p + 1], accp[i][p]);
        float4 o0 = make_float4(v[0] + bias[0], v[1] + bias[1],
                                v[2] + bias[2], v[3] + bias[3]);
        float4 o1 = make_float4(v[4] + bias[4], v[5] + bias[5],
                                v[6] + bias[6], v[7] + bias[7]);
        *(float4*)&g_wx0[(size_t)m * G4 + gbase]     = o0;
        *(float4*)&g_wx0[(size_t)m * G4 + gbase + 4] = o1;
    }
}

extern "C" void kernel_launch(void* const* d_in, const int* in_sizes, int n_in,
                              void* d_out, int out_size)
{
    const float* x    = (const float*)d_in[0];
    const float* w0_w = (const float*)d_in[1];
    const float* w0_b = (const float*)d_in[2];
    const float* u0_w = (const float*)d_in[3];
    const float* u0_b = (const float*)d_in[4];
    const float* w1_w = (const float*)d_in[5];
    const float* w1_b = (const float*)d_in[6];
    const float* u1_w = (const float*)d_in[7];
    const float* u1_b = (const float*)d_in[8];
    float* out = (float*)d_out;

    static int attr_done = 0;
    if (!attr_done) {
        cudaFuncSetAttribute(lstm_persist, cudaFuncAttributeMaxDynamicSharedMemorySize, SMEM_BYTES);
        attr_done = 1;
    }

    wx_gemm<<<dim3(G4 / 128, MM / 128), 256>>>(x, w0_w, w0_b, u0_b);
    lstm_persist<<<NCTA, 256, SMEM_BYTES>>>(u0_w, w1_w, u1_w, w1_b, u1_b, out);
}

// round 15
// speedup vs baseline: 1.0986x; 1.0430x over previous
#include <cuda_runtime.h>
#include <cuda_bf16.h>
#include <math.h>

// Problem constants
#define BB 8
#define TT 2048
#define DIN 256
#define HH 512
#define G4 2048          // 4*H
#define MM (BB*TT)       // 16384
#define NCTA 96          // barrier participants (32 L0 + 64 L1)
#define L0_CTAS 32
#define GEMM_CTAS 52
#define GRID_TOTAL 148

// ---------------- device scratch ----------------
__device__ float g_wx0[(size_t)MM * G4];   // 128 MB: x@W0^T + (w0_b+u0_b)
__device__ float g_h1[2][HH * BB];         // ping-pong h of layer0, layout [j][b]
__device__ float g_h2[2][HH * BB];         // ping-pong h of layer1
__device__ unsigned g_bar;                 // global barrier counter
__device__ unsigned g_chunkcnt[16 * 32];   // per-chunk completion counters (128B stride)

// ---------------- shared memory layout (floats) ----------------
// persist: wS [K][SW] | srcS [K][8] | redS [NKG*R4][36]
// gemm   : As [16][128] | Bs [16][128]
#define OFF_SRC  36864
#define OFF_RED  45056
#define SMEM_FLOATS 54272
#define SMEM_BYTES (SMEM_FLOATS * 4)   // 217088 < 227KB limit

typedef unsigned long long u64;

__device__ __forceinline__ u64 pk2(float x) {
    u64 r; asm("mov.b64 %0, {%1, %1};" : "=l"(r) : "f"(x)); return r;
}
__device__ __forceinline__ void fma2(u64& a, u64 b, u64 c) {
    asm("fma.rn.f32x2 %0, %1, %2, %0;" : "+l"(a) : "l"(b), "l"(c));
}
__device__ __forceinline__ u64 addp(u64 a, u64 b) {
    u64 r; asm("add.rn.f32x2 %0, %1, %2;" : "=l"(r) : "l"(a), "l"(b)); return r;
}
__device__ __forceinline__ void upk(float& lo, float& hi, u64 v) {
    asm("mov.b64 {%0, %1}, %2;" : "=f"(lo), "=f"(hi) : "l"(v));
}
__device__ __forceinline__ float4 ldcg4(const float4* p) { return __ldcg(p); }
__device__ __forceinline__ float fast_sig(float x) {
    return __fdividef(1.f, 1.f + __expf(-x));
}
__device__ __forceinline__ float fast_tanh(float x) {
    float e = __expf(2.f * x);
    return 1.f - __fdividef(2.f, e + 1.f);
}
__device__ __forceinline__ void wait_chunk(int c) {
    const unsigned* p = &g_chunkcnt[c * 32];
    unsigned v;
    do {
        asm volatile("ld.acquire.gpu.global.u32 %0, [%1];" : "=r"(v) : "l"(p) : "memory");
    } while (v < (unsigned)GEMM_CTAS);
}

// 4 packed FMAs: acc[AOFF..AOFF+3] += (w,w) * hpairs
#define FMA_ROW2(AOFF, WV)                                   \
    { u64 wp = pk2(WV);                                      \
      fma2(acc[AOFF+0], wp, hA.x); fma2(acc[AOFF+1], wp, hA.y); \
      fma2(acc[AOFF+2], wp, hB.x); fma2(acc[AOFF+3], wp, hB.y); }

template <int LAYER, int R, int K, int U>
__device__ void run_layer(const float* __restrict__ wA,
                          const float* __restrict__ wB,
                          const float* __restrict__ bA,
                          const float* __restrict__ bB,
                          int ubase, float* sm, float* __restrict__ out)
{
    const int t = threadIdx.x;
    const int lane = t & 31;
    const int w = t >> 5;
    constexpr int R4  = R / 4;
    constexpr int SW  = R + 4;
    constexpr int NKG = 256 / R4;    // 16 (L0) / 32 (L1)
    constexpr int KCH = K / NKG;     // 32 both
    constexpr int KSH = (K == 512) ? 9 : 10;
    constexpr int UPD = U * 8;       // 128 (L0) / 64 (L1)

    float* wS   = sm;
    float* srcS = sm + OFF_SRC;
    float* redS = sm + OFF_RED;

    // ---- one-time weight load (transposed [k][row], padded) ----
    // UNIT-MAJOR row order: local row rr -> unit rr>>2, gate rr&3
    for (int e = t; e < R * K; e += 256) {
        int k  = e & (K - 1);
        int rr = e >> KSH;
        int g  = (rr & 3) * 512 + ubase + (rr >> 2);
        float v;
        if (LAYER == 0) v = wA[g * 512 + k];
        else            v = (k < 512) ? wA[g * 512 + k] : wB[g * 512 + (k - 512)];
        wS[k * SW + rr] = v;
    }

    const int uu = t >> 3;
    const int ub = t & 7;

    float biasv[4] = {0.f, 0.f, 0.f, 0.f};
    if (LAYER == 1 && t < UPD) {
        #pragma unroll
        for (int g = 0; g < 4; ++g) {
            int gi = g * 512 + ubase + uu;
            biasv[g] = bA[gi] + bB[gi];
        }
    }
    __syncthreads();

    float c_state = 0.f;
    const int jg = t & (R4 - 1);
    const int kg = t >> ((LAYER == 0) ? 4 : 3);

    // wx prefetch (L0 only): wait for chunk 0, then load round 0
    float wxv[4] = {0.f, 0.f, 0.f, 0.f};
    const float* wxrow = (LAYER == 0)
        ? &g_wx0[((size_t)(ub * TT)) * G4 + ubase + uu] : nullptr;
    if (LAYER == 0 && t < UPD) {
        wait_chunk(0);
        #pragma unroll
        for (int g = 0; g < 4; ++g) wxv[g] = __ldcg(wxrow + g * 512);
    }

    for (int r = 0; r <= TT; ++r) {
        const bool active = (LAYER == 0) ? (r < TT) : (r >= 1);

        if (active) {
            const int slot = (r + 1) & 1;   // (r-1) mod 2
            // slice-aligned warp-local stage
            float4* dst = (float4*)srcS;
            if (LAYER == 0) {
                const float4* s1 = (const float4*)g_h1[slot];
                const int base = 128 * w + lane;
                dst[base]      = ldcg4(s1 + base);
                dst[base + 32] = ldcg4(s1 + base + 32);
                dst[base + 64] = ldcg4(s1 + base + 64);
                dst[base + 96] = ldcg4(s1 + base + 96);
            } else {
                const float4* s1 = (const float4*)g_h1[slot];
                const float4* s2 = (const float4*)g_h2[slot];
                const float4* src = (w < 4) ? (s1 + 256 * w) : (s2 + 256 * (w - 4));
                float4* d = dst + 256 * w;
                #pragma unroll
                for (int i = 0; i < 8; ++i)
                    d[lane + i * 32] = ldcg4(src + lane + i * 32);
            }
            __syncwarp();

            u64 acc[16];
            #pragma unroll
            for (int i = 0; i < 16; ++i) acc[i] = 0ull;
            const float4* w4 = (const float4*)wS;
            const int kbase = kg * KCH;
            #pragma unroll 8
            for (int kk = 0; kk < KCH; ++kk) {
                const int k = kbase + kk;
                float4 wv = w4[k * (SW / 4) + jg];
                const ulonglong2* hsrc = (const ulonglong2*)(srcS + k * 8);
                ulonglong2 hA = hsrc[0];   // batch pairs (0,1),(2,3)
                ulonglong2 hB = hsrc[1];   // batch pairs (4,5),(6,7)
                FMA_ROW2(0,  wv.x)
                FMA_ROW2(4,  wv.y)
                FMA_ROW2(8,  wv.z)
                FMA_ROW2(12, wv.w)
            }
            // pair-major partial store: u64 index p*4+g, 8 x STS.128
            ulonglong2* rb = (ulonglong2*)(redS + (kg * R4 + jg) * 36);
            #pragma unroll
            for (int j = 0; j < 8; ++j) {
                const int p = j >> 1, g0 = (j & 1) * 2;
                rb[j] = make_ulonglong2(acc[g0 * 4 + p], acc[(g0 + 1) * 4 + p]);
            }
        }
        __syncthreads();   // redS ready for the merged tail

        float h_def = 0.f;   // deferred output value (L1)
        if (active && t < UPD) {
            // packed tail reduce: 2 x LDS.128 per k-group, f32x2 adds
            const int p = ub >> 1, hb = ub & 1;
            u64 sp0 = 0ull, sp1 = 0ull, sp2 = 0ull, sp3 = 0ull;
            #pragma unroll
            for (int k2 = 0; k2 < NKG; ++k2) {
                const ulonglong2* rbase =
                    (const ulonglong2*)(redS + (k2 * R4 + uu) * 36 + p * 8);
                ulonglong2 v0 = rbase[0];
                ulonglong2 v1 = rbase[1];
                sp0 = addp(sp0, v0.x); sp1 = addp(sp1, v0.y);
                sp2 = addp(sp2, v1.x); sp3 = addp(sp3, v1.y);
            }
            float s4[4];
            {
                float lo, hi;
                upk(lo, hi, sp0); s4[0] = hb ? hi : lo;
                upk(lo, hi, sp1); s4[1] = hb ? hi : lo;
                upk(lo, hi, sp2); s4[2] = hb ? hi : lo;
                upk(lo, hi, sp3); s4[3] = hb ? hi : lo;
            }
            #pragma unroll
            for (int g = 0; g < 4; ++g)
                s4[g] += (LAYER == 0) ? wxv[g] : biasv[g];

            float si = fast_sig(s4[0]);
            float sf = fast_sig(s4[1]);
            float tg = fast_tanh(s4[2]);
            float so = fast_sig(s4[3]);
            c_state = sf * c_state + si * tg;
            float h = so * fmaxf(c_state, 0.f);
            const int j = ubase + uu;
            const int slotw = r & 1;
            if (LAYER == 0) {
                __stcg(&g_h1[slotw][j * 8 + ub], h);
                if (r == TT - 1) {
                    out[8388608 + ub * 512 + j] = h;        // hh[0]
                    out[8396800 + ub * 512 + j] = c_state;  // cc[0]
                }
            } else {
                __stcg(&g_h2[slotw][j * 8 + ub], h);
                h_def = h;
                if (r == TT) {   // last epoch: no barrier follows, store now
                    out[((size_t)(ub * TT + (r - 1))) * HH + j] = h;
                    out[8388608 + 4096 + ub * 512 + j] = h;        // hh[1]
                    out[8396800 + 4096 + ub * 512 + j] = c_state;  // cc[1]
                }
            }
        }

        // prefetch next round's wx (lands during the barrier spin);
        // gate at chunk boundaries (once per 128 rounds)
        if (LAYER == 0 && t < UPD && r + 1 < TT) {
            const int rn = r + 1;
            if ((rn & 127) == 0) wait_chunk(rn >> 7);
            const float* p = wxrow + (size_t)rn * G4;
            #pragma unroll
            for (int g = 0; g < 4; ++g) wxv[g] = __ldcg(p + g * 512);
        }

        if (r < TT) {
            if (t < UPD) asm volatile("bar.sync 1, %0;" :: "n"(UPD) : "memory");
            if (t == 0)
                asm volatile("red.release.gpu.global.add.u32 [%0], 1;"
                             :: "l"(&g_bar) : "memory");
            // deferred output store: overlaps t0's spin
            if (LAYER == 1 && active && t < UPD) {
                const int j = ubase + uu;
                out[((size_t)(ub * TT + (r - 1))) * HH + j] = h_def;
            }
            if (t == 0) {
                const unsigned target = (unsigned)NCTA * (unsigned)(r + 1);
                unsigned v;
                do {
                    asm volatile("ld.acquire.gpu.global.u32 %0, [%1];"
                                 : "=r"(v) : "l"(&g_bar) : "memory");
                } while (v < target);
            }
            __syncthreads();
        }
    }
}

// ---------------- GEMM worker: wx0 tiles in r-chunk-major order ----------------
__device__ void gemm_worker(const float* __restrict__ X, const float* __restrict__ W,
                            const float* __restrict__ b0, const float* __restrict__ ub0,
                            int g, float* sm)
{
    float* As = sm;          // [16][128]
    float* Bs = sm + 2048;   // [16][128]
    const int t = threadIdx.x;
    const int tm = t & 15, tn = t >> 4;

    for (int c = 0; c < 16; ++c) {
        for (int tile = g; tile < 128; tile += GEMM_CTAS) {
            const int b  = tile >> 4;
            const int bn = tile & 15;
            const int bm = b * 16 + c;

            u64 accp[8][4];
            #pragma unroll
            for (int i = 0; i < 8; ++i)
                #pragma unroll
                for (int j = 0; j < 4; ++j) accp[i][j] = 0ull;

            for (int kt = 0; kt < DIN; kt += 16) {
                #pragma unroll
                for (int i = 0; i < 2; ++i) {
                    int f = t * 2 + i;
                    int row = f >> 2, kq = f & 3;
                    float4 a = *(const float4*)&X[(size_t)(bm * 128 + row) * DIN + kt + kq * 4];
                    As[(kq * 4 + 0) * 128 + row] = a.x;
                    As[(kq * 4 + 1) * 128 + row] = a.y;
                    As[(kq * 4 + 2) * 128 + row] = a.z;
                    As[(kq * 4 + 3) * 128 + row] = a.w;
                    float4 bv = *(const float4*)&W[(size_t)(bn * 128 + row) * DIN + kt + kq * 4];
                    Bs[(kq * 4 + 0) * 128 + row] = bv.x;
                    Bs[(kq * 4 + 1) * 128 + row] = bv.y;
                    Bs[(kq * 4 + 2) * 128 + row] = bv.z;
                    Bs[(kq * 4 + 3) * 128 + row] = bv.w;
                }
                __syncthreads();
                #pragma unroll
                for (int k = 0; k < 16; ++k) {
                    float4 a0 = *(const float4*)&As[k * 128 + tm * 8];
                    float4 a1 = *(const float4*)&As[k * 128 + tm * 8 + 4];
                    const ulonglong2* bp = (const ulonglong2*)&Bs[k * 128 + tn * 8];
                    ulonglong2 c01 = bp[0];
                    ulonglong2 c23 = bp[1];
                    float av[8] = {a0.x, a0.y, a0.z, a0.w, a1.x, a1.y, a1.z, a1.w};
                    #pragma unroll
                    for (int i = 0; i < 8; ++i) {
                        u64 wp = pk2(av[i]);
                        fma2(accp[i][0], wp, c01.x);
                        fma2(accp[i][1], wp, c01.y);
                        fma2(accp[i][2], wp, c23.x);
                        fma2(accp[i][3], wp, c23.y);
                    }
                }
                __syncthreads();
            }

            const int gbase = bn * 128 + tn * 8;
            float bias[8];
            #pragma unroll
            for (int j = 0; j < 8; ++j)
                bias[j] = __ldg(&b0[gbase + j]) + __ldg(&ub0[gbase + j]);
            #pragma unroll
            for (int i = 0; i < 8; ++i) {
                const int m = bm * 128 + tm * 8 + i;
                float v[8];
                #pragma unroll
                for (int p = 0; p < 4; ++p) upk(v[2 * p], v[2 * p + 1], accp[i][p]);
                float4 o0 = make_float4(v[0] + bias[0], v[1] + bias[1],
                                        v[2] + bias[2], v[3] + bias[3]);
                float4 o1 = make_float4(v[4] + bias[4], v[5] + bias[5],
                                        v[6] + bias[6], v[7] + bias[7]);
                *(float4*)&g_wx0[(size_t)m * G4 + gbase]     = o0;
                *(float4*)&g_wx0[(size_t)m * G4 + gbase + 4] = o1;
            }
        }
        // all this CTA's tiles of chunk c done -> arrive
        if (t == 0)
            asm volatile("red.release.gpu.global.add.u32 [%0], 1;"
                         :: "l"(&g_chunkcnt[c * 32]) : "memory");
    }
}

__global__ void __launch_bounds__(256, 1)
lstm_persist(const float* __restrict__ x,
             const float* __restrict__ w0w, const float* __restrict__ w0b,
             const float* __restrict__ u0w, const float* __restrict__ u0b,
             const float* __restrict__ w1w, const float* __restrict__ w1b,
             const float* __restrict__ u1w, const float* __restrict__ u1b,
             float* __restrict__ out)
{
    extern __shared__ float sm[];
    const int cta = blockIdx.x;
    if (cta < L0_CTAS) {
        run_layer<0, 64, 512, 16>(u0w, nullptr, nullptr, nullptr, cta * 16, sm, out);
    } else if (cta < NCTA) {
        run_layer<1, 32, 1024, 8>(w1w, u1w, w1b, u1b, (cta - L0_CTAS) * 8, sm, out);
    } else {
        gemm_worker(x, w0w, w0b, u0b, cta - NCTA, sm);
    }
}

__global__ void init_k() {
    int t = threadIdx.x;
    float* h1f = (float*)g_h1;
    float* h2f = (float*)g_h2;
    for (int i = t; i < 2 * HH * BB; i += 256) { h1f[i] = 0.f; h2f[i] = 0.f; }
    if (t == 0) g_bar = 0u;
    if (t < 16) g_chunkcnt[t * 32] = 0u;
}

extern "C" void kernel_launch(void* const* d_in, const int* in_sizes, int n_in,
                              void* d_out, int out_size)
{
    const float* x    = (const float*)d_in[0];
    const float* w0_w = (const float*)d_in[1];
    const float* w0_b = (const float*)d_in[2];
    const float* u0_w = (const float*)d_in[3];
    const float* u0_b = (const float*)d_in[4];
    const float* w1_w = (const float*)d_in[5];
    const float* w1_b = (const float*)d_in[6];
    const float* u1_w = (const float*)d_in[7];
    const float* u1_b = (const float*)d_in[8];
    float* out = (float*)d_out;

    static int attr_done = 0;
    if (!attr_done) {
        cudaFuncSetAttribute(lstm_persist, cudaFuncAttributeMaxDynamicSharedMemorySize, SMEM_BYTES);
        attr_done = 1;
    }

    init_k<<<1, 256>>>();
    lstm_persist<<<GRID_TOTAL, 256, SMEM_BYTES>>>(x, w0_w, w0_b, u0_w, u0_b,
                                                  w1_w, w1_b, u1_w, u1_b, out);
}